// round 1
// baseline (speedup 1.0000x reference)
#include <cuda_runtime.h>
#include <cuda_bf16.h>

#define N_NODES 50000
#define N_EDGES 1600000
#define D_IN 512
#define H 64

// ---------------- scratch (static device allocations; no cudaMalloc) ----------------
__device__ float g_deg[N_NODES];
__device__ float g_dinv[N_NODES];
__device__ int   g_count[N_NODES];
__device__ int   g_start[N_NODES + 1];
__device__ int   g_cursor[N_NODES];
__device__ int   g_src[N_EDGES];
__device__ float g_nrm[N_EDGES];
__device__ float g_bufA[N_NODES * H];   // transformed features
__device__ float g_bufB[N_NODES * H];   // aggregated/activated features

__device__ __forceinline__ float selu_f(float x) {
    const float sc = 1.0507009873554805f;
    const float al = 1.6732632423543772f;
    return x > 0.0f ? sc * x : sc * al * (expf(x) - 1.0f);
}

// ---------------- degree / CSR construction ----------------
__global__ void k_init() {
    int i = blockIdx.x * blockDim.x + threadIdx.x;
    if (i < N_NODES) {
        g_deg[i] = 1.0f;     // self-loop weight
        g_count[i] = 0;
    }
}

__global__ void k_deg_hist(const int* __restrict__ ei, const float* __restrict__ ew) {
    int e = blockIdx.x * blockDim.x + threadIdx.x;
    if (e < N_EDGES) {
        int c = ei[N_EDGES + e];           // target
        atomicAdd(&g_deg[c], ew[e]);
        atomicAdd(&g_count[c], 1);
    }
}

__global__ void k_dinv() {
    int i = blockIdx.x * blockDim.x + threadIdx.x;
    if (i < N_NODES) {
        float d = g_deg[i];
        g_dinv[i] = (d > 0.0f) ? rsqrtf(d) : 0.0f;
    }
}

// single-block exclusive scan over g_count -> g_start, g_cursor
__global__ void k_scan() {
    __shared__ int sums[1024];
    const int CH = (N_NODES + 1023) / 1024;   // 49
    int t = threadIdx.x;
    int base = t * CH;
    int local = 0;
    for (int j = 0; j < CH; j++) {
        int idx = base + j;
        if (idx < N_NODES) local += g_count[idx];
    }
    sums[t] = local;
    __syncthreads();
    for (int off = 1; off < 1024; off <<= 1) {
        int v = 0;
        if (t >= off) v = sums[t - off];
        __syncthreads();
        if (t >= off) sums[t] += v;
        __syncthreads();
    }
    int prefix = (t == 0) ? 0 : sums[t - 1];
    for (int j = 0; j < CH; j++) {
        int idx = base + j;
        if (idx < N_NODES) {
            g_start[idx] = prefix;
            g_cursor[idx] = prefix;
            prefix += g_count[idx];
        }
    }
    if (t == 1023) g_start[N_NODES] = N_EDGES;
}

__global__ void k_scatter(const int* __restrict__ ei, const float* __restrict__ ew) {
    int e = blockIdx.x * blockDim.x + threadIdx.x;
    if (e < N_EDGES) {
        int r = ei[e];
        int c = ei[N_EDGES + e];
        int pos = atomicAdd(&g_cursor[c], 1);
        g_src[pos] = r;
        g_nrm[pos] = g_dinv[r] * ew[e] * g_dinv[c];
    }
}

// ---------------- GEMM: [N,512] @ [512,64] -> g_bufA ----------------
__global__ void k_gemm512(const float* __restrict__ A, const float* __restrict__ W) {
    __shared__ float As[32][65];   // [k][m]
    __shared__ float Bs[32][64];   // [k][n]
    int m0 = blockIdx.x * 64;
    int tid = threadIdx.x;
    int ty = tid >> 4, tx = tid & 15;
    float acc[4][4] = {};
    for (int k0 = 0; k0 < D_IN; k0 += 32) {
        #pragma unroll
        for (int l = 0; l < 2; l++) {
            int fi = l * 256 + tid;        // 0..511 float4s of A tile
            int m = fi >> 3;               // 0..63
            int kq = fi & 7;               // 0..7
            float4 v = make_float4(0.f, 0.f, 0.f, 0.f);
            if (m0 + m < N_NODES)
                v = *(const float4*)&A[(size_t)(m0 + m) * D_IN + k0 + kq * 4];
            As[kq * 4 + 0][m] = v.x;
            As[kq * 4 + 1][m] = v.y;
            As[kq * 4 + 2][m] = v.z;
            As[kq * 4 + 3][m] = v.w;
        }
        #pragma unroll
        for (int l = 0; l < 2; l++) {
            int fi = l * 256 + tid;        // 0..511 float4s of W tile
            int r = fi >> 4;               // 0..31
            int cq = fi & 15;              // 0..15
            float4 v = *(const float4*)&W[(k0 + r) * 64 + cq * 4];
            *(float4*)&Bs[r][cq * 4] = v;
        }
        __syncthreads();
        #pragma unroll
        for (int kk = 0; kk < 32; kk++) {
            float a[4];
            #pragma unroll
            for (int i = 0; i < 4; i++) a[i] = As[kk][ty * 4 + i];
            float4 b = *(float4*)&Bs[kk][tx * 4];
            #pragma unroll
            for (int i = 0; i < 4; i++) {
                acc[i][0] = fmaf(a[i], b.x, acc[i][0]);
                acc[i][1] = fmaf(a[i], b.y, acc[i][1]);
                acc[i][2] = fmaf(a[i], b.z, acc[i][2]);
                acc[i][3] = fmaf(a[i], b.w, acc[i][3]);
            }
        }
        __syncthreads();
    }
    #pragma unroll
    for (int i = 0; i < 4; i++) {
        int row = m0 + ty * 4 + i;
        if (row < N_NODES) {
            float4 v = make_float4(acc[i][0], acc[i][1], acc[i][2], acc[i][3]);
            *(float4*)&g_bufA[(size_t)row * H + tx * 4] = v;
        }
    }
}

// ---------------- aggregation: g_bufA -> selu(segsum + bias) -> g_bufB ----------------
__global__ void k_aggregate(const float* __restrict__ bias) {
    int gwarp = (blockIdx.x * blockDim.x + threadIdx.x) >> 5;
    int lane = threadIdx.x & 31;
    if (gwarp >= N_NODES) return;
    int node = gwarp;
    int s = g_start[node];
    int e = g_start[node + 1];
    float dv = g_dinv[node];
    const float2* xin = (const float2*)g_bufA;
    float2 sv = xin[node * 32 + lane];
    float nself = dv * dv;
    float2 acc;
    acc.x = sv.x * nself;
    acc.y = sv.y * nself;
    int j = s;
    for (; j + 1 < e; j += 2) {
        int s0 = g_src[j], s1 = g_src[j + 1];
        float n0 = g_nrm[j], n1 = g_nrm[j + 1];
        float2 v0 = xin[s0 * 32 + lane];
        float2 v1 = xin[s1 * 32 + lane];
        acc.x = fmaf(v0.x, n0, acc.x);
        acc.y = fmaf(v0.y, n0, acc.y);
        acc.x = fmaf(v1.x, n1, acc.x);
        acc.y = fmaf(v1.y, n1, acc.y);
    }
    if (j < e) {
        int s0 = g_src[j];
        float n0 = g_nrm[j];
        float2 v0 = xin[s0 * 32 + lane];
        acc.x = fmaf(v0.x, n0, acc.x);
        acc.y = fmaf(v0.y, n0, acc.y);
    }
    float b0 = bias[2 * lane], b1 = bias[2 * lane + 1];
    float2 r;
    r.x = selu_f(acc.x + b0);
    r.y = selu_f(acc.y + b1);
    ((float2*)g_bufB)[node * 32 + lane] = r;
}

// ---------------- 64x64 transform: g_bufB @ W -> g_bufA (no bias/act) ----------------
__global__ void k_dense64(const float* __restrict__ W) {
    __shared__ float hs[64][68];
    __shared__ float ws[64][64];
    int m0 = blockIdx.x * 64;
    int tid = threadIdx.x;
    int ty = tid >> 4, tx = tid & 15;
    #pragma unroll
    for (int l = 0; l < 4; l++) {
        int fi = l * 256 + tid;   // 1024 float4s
        int r = fi >> 4;
        int cq = fi & 15;
        float4 v = make_float4(0.f, 0.f, 0.f, 0.f);
        if (m0 + r < N_NODES) v = *(const float4*)&g_bufB[(size_t)(m0 + r) * H + cq * 4];
        *(float4*)&hs[r][cq * 4] = v;
        *(float4*)&ws[r][cq * 4] = *(const float4*)&W[r * 64 + cq * 4];
    }
    __syncthreads();
    float acc[4][4] = {};
    #pragma unroll 4
    for (int k = 0; k < 64; k++) {
        float a[4];
        #pragma unroll
        for (int i = 0; i < 4; i++) a[i] = hs[ty * 4 + i][k];
        float4 b = *(float4*)&ws[k][tx * 4];
        #pragma unroll
        for (int i = 0; i < 4; i++) {
            acc[i][0] = fmaf(a[i], b.x, acc[i][0]);
            acc[i][1] = fmaf(a[i], b.y, acc[i][1]);
            acc[i][2] = fmaf(a[i], b.z, acc[i][2]);
            acc[i][3] = fmaf(a[i], b.w, acc[i][3]);
        }
    }
    #pragma unroll
    for (int i = 0; i < 4; i++) {
        int row = m0 + ty * 4 + i;
        if (row < N_NODES) {
            float4 v = make_float4(acc[i][0], acc[i][1], acc[i][2], acc[i][3]);
            *(float4*)&g_bufA[(size_t)row * H + tx * 4] = v;
        }
    }
}

// ---------------- fused 4-layer MLP: g_bufB -> out ----------------
__global__ void k_mlp4(const float* __restrict__ W0, const float* __restrict__ b0,
                       const float* __restrict__ W1, const float* __restrict__ b1,
                       const float* __restrict__ W2, const float* __restrict__ b2,
                       const float* __restrict__ W3, const float* __restrict__ b3,
                       float* __restrict__ out) {
    __shared__ float hs[64][68];
    __shared__ float ws[64][64];
    int m0 = blockIdx.x * 64;
    int tid = threadIdx.x;
    int ty = tid >> 4, tx = tid & 15;

    #pragma unroll
    for (int l = 0; l < 4; l++) {
        int fi = l * 256 + tid;
        int r = fi >> 4;
        int cq = fi & 15;
        float4 v = make_float4(0.f, 0.f, 0.f, 0.f);
        if (m0 + r < N_NODES) v = *(const float4*)&g_bufB[(size_t)(m0 + r) * H + cq * 4];
        *(float4*)&hs[r][cq * 4] = v;
    }

    const float* Wl[4] = {W0, W1, W2, W3};
    const float* bl[4] = {b0, b1, b2, b3};

    #pragma unroll
    for (int L = 0; L < 4; L++) {
        __syncthreads();
        #pragma unroll
        for (int l = 0; l < 4; l++) {
            int fi = l * 256 + tid;
            *(float4*)&ws[0][fi * 4] = *(const float4*)&Wl[L][fi * 4];
        }
        __syncthreads();
        float acc[4][4] = {};
        #pragma unroll 4
        for (int k = 0; k < 64; k++) {
            float a[4];
            #pragma unroll
            for (int i = 0; i < 4; i++) a[i] = hs[ty * 4 + i][k];
            float4 b = *(float4*)&ws[k][tx * 4];
            #pragma unroll
            for (int i = 0; i < 4; i++) {
                acc[i][0] = fmaf(a[i], b.x, acc[i][0]);
                acc[i][1] = fmaf(a[i], b.y, acc[i][1]);
                acc[i][2] = fmaf(a[i], b.z, acc[i][2]);
                acc[i][3] = fmaf(a[i], b.w, acc[i][3]);
            }
        }
        float4 bb = *(const float4*)&bl[L][tx * 4];
        __syncthreads();
        if (L < 3) {
            #pragma unroll
            for (int i = 0; i < 4; i++) {
                hs[ty * 4 + i][tx * 4 + 0] = selu_f(acc[i][0] + bb.x);
                hs[ty * 4 + i][tx * 4 + 1] = selu_f(acc[i][1] + bb.y);
                hs[ty * 4 + i][tx * 4 + 2] = selu_f(acc[i][2] + bb.z);
                hs[ty * 4 + i][tx * 4 + 3] = selu_f(acc[i][3] + bb.w);
            }
        } else {
            #pragma unroll
            for (int i = 0; i < 4; i++) {
                int row = m0 + ty * 4 + i;
                if (row < N_NODES) {
                    float4 v = make_float4(acc[i][0] + bb.x, acc[i][1] + bb.y,
                                           acc[i][2] + bb.z, acc[i][3] + bb.w);
                    *(float4*)&out[(size_t)row * H + tx * 4] = v;
                }
            }
        }
    }
}

// ---------------- launch ----------------
extern "C" void kernel_launch(void* const* d_in, const int* in_sizes, int n_in,
                              void* d_out, int out_size) {
    const float* x   = (const float*)d_in[0];
    const int*   ei  = (const int*)d_in[1];
    const float* ea  = (const float*)d_in[2];
    const float* gW1 = (const float*)d_in[3];
    const float* gb1 = (const float*)d_in[4];
    const float* gW2 = (const float*)d_in[5];
    const float* gb2 = (const float*)d_in[6];
    const float* W0  = (const float*)d_in[7];
    const float* b0  = (const float*)d_in[8];
    const float* W1  = (const float*)d_in[9];
    const float* b1  = (const float*)d_in[10];
    const float* W2  = (const float*)d_in[11];
    const float* b2  = (const float*)d_in[12];
    const float* W3  = (const float*)d_in[13];
    const float* b3  = (const float*)d_in[14];
    float* out = (float*)d_out;

    const int nodeBlocks = (N_NODES + 255) / 256;     // 196
    const int edgeBlocks = (N_EDGES + 255) / 256;     // 6250
    const int tileBlocks = (N_NODES + 63) / 64;       // 782
    const int warpBlocks = (N_NODES * 32 + 255) / 256;// 6250

    // CSR build (shared by both GCN layers)
    k_init<<<nodeBlocks, 256>>>();
    k_deg_hist<<<edgeBlocks, 256>>>(ei, ea);
    k_dinv<<<nodeBlocks, 256>>>();
    k_scan<<<1, 1024>>>();
    k_scatter<<<edgeBlocks, 256>>>(ei, ea);

    // GCN layer 1
    k_gemm512<<<tileBlocks, 256>>>(x, gW1);
    k_aggregate<<<warpBlocks, 256>>>(gb1);
    // GCN layer 2
    k_dense64<<<tileBlocks, 256>>>(gW2);
    k_aggregate<<<warpBlocks, 256>>>(gb2);
    // fused MLP
    k_mlp4<<<tileBlocks, 256>>>(W0, b0, W1, b1, W2, b2, W3, b3, out);
}

// round 2
// speedup vs baseline: 1.2361x; 1.2361x over previous
#include <cuda_runtime.h>
#include <cuda_bf16.h>

#define N_NODES 50000
#define N_EDGES 1600000
#define D_IN 512
#define H 64

#define SCAN_BLOCKS 196   // ceil(50000/256)

// ---------------- scratch (static device allocations; no cudaMalloc) ----------------
__device__ float g_deg[N_NODES];
__device__ float g_dinv[N_NODES];
__device__ int   g_count[N_NODES];
__device__ int   g_start[N_NODES + 1];
__device__ int   g_cursor[N_NODES];
__device__ int   g_bsum[SCAN_BLOCKS];
__device__ int   g_boff[SCAN_BLOCKS];
__device__ int   g_src[N_EDGES];
__device__ float g_nrm[N_EDGES];
__device__ float g_bufA[N_NODES * H];   // transformed features
__device__ float g_bufB[N_NODES * H];   // aggregated/activated features

__device__ __forceinline__ float selu_f(float x) {
    const float sc = 1.0507009873554805f;
    const float al = 1.6732632423543772f;
    return x > 0.0f ? sc * x : sc * al * (expf(x) - 1.0f);
}

// ---------------- degree / CSR construction ----------------
__global__ void k_init() {
    int i = blockIdx.x * blockDim.x + threadIdx.x;
    if (i < N_NODES) {
        g_deg[i] = 1.0f;     // self-loop weight
        g_count[i] = 0;
    }
}

__global__ void k_deg_hist(const int* __restrict__ ei, const float* __restrict__ ew) {
    int e = blockIdx.x * blockDim.x + threadIdx.x;
    if (e < N_EDGES) {
        int c = ei[N_EDGES + e];           // target
        atomicAdd(&g_deg[c], ew[e]);
        atomicAdd(&g_count[c], 1);
    }
}

__global__ void k_dinv() {
    int i = blockIdx.x * blockDim.x + threadIdx.x;
    if (i < N_NODES) {
        float d = g_deg[i];
        g_dinv[i] = (d > 0.0f) ? rsqrtf(d) : 0.0f;
    }
}

// ---------------- 3-phase grid scan over g_count -> g_start, g_cursor ----------------
// phase 1: per-block sums (196 blocks x 256)
__global__ void k_scan1() {
    __shared__ int s[256];
    int i = blockIdx.x * 256 + threadIdx.x;
    int v = (i < N_NODES) ? g_count[i] : 0;
    s[threadIdx.x] = v;
    __syncthreads();
    #pragma unroll
    for (int off = 128; off > 0; off >>= 1) {
        if (threadIdx.x < off) s[threadIdx.x] += s[threadIdx.x + off];
        __syncthreads();
    }
    if (threadIdx.x == 0) g_bsum[blockIdx.x] = s[0];
}

// phase 2: exclusive scan of 196 block sums (1 block of 256)
__global__ void k_scan2() {
    __shared__ int s[256];
    int t = threadIdx.x;
    s[t] = (t < SCAN_BLOCKS) ? g_bsum[t] : 0;
    __syncthreads();
    #pragma unroll
    for (int off = 1; off < 256; off <<= 1) {
        int v = 0;
        if (t >= off) v = s[t - off];
        __syncthreads();
        if (t >= off) s[t] += v;
        __syncthreads();
    }
    if (t < SCAN_BLOCKS) g_boff[t] = (t == 0) ? 0 : s[t - 1];
}

// phase 3: per-block exclusive scan + block offset
__global__ void k_scan3() {
    __shared__ int s[256];
    int t = threadIdx.x;
    int i = blockIdx.x * 256 + t;
    int v = (i < N_NODES) ? g_count[i] : 0;
    s[t] = v;
    __syncthreads();
    #pragma unroll
    for (int off = 1; off < 256; off <<= 1) {
        int u = 0;
        if (t >= off) u = s[t - off];
        __syncthreads();
        if (t >= off) s[t] += u;
        __syncthreads();
    }
    if (i < N_NODES) {
        int excl = g_boff[blockIdx.x] + s[t] - v;   // inclusive - self = exclusive
        g_start[i] = excl;
        g_cursor[i] = excl;
    }
    if (i == N_NODES - 1) g_start[N_NODES] = N_EDGES;
}

__global__ void k_scatter(const int* __restrict__ ei, const float* __restrict__ ew) {
    int e = blockIdx.x * blockDim.x + threadIdx.x;
    if (e < N_EDGES) {
        int r = ei[e];
        int c = ei[N_EDGES + e];
        int pos = atomicAdd(&g_cursor[c], 1);
        g_src[pos] = r;
        g_nrm[pos] = g_dinv[r] * ew[e] * g_dinv[c];
    }
}

// ---------------- GEMM: [N,512] @ [512,64] -> g_bufA ----------------
__global__ void k_gemm512(const float* __restrict__ A, const float* __restrict__ W) {
    __shared__ float As[32][65];   // [k][m]
    __shared__ float Bs[32][64];   // [k][n]
    int m0 = blockIdx.x * 64;
    int tid = threadIdx.x;
    int ty = tid >> 4, tx = tid & 15;
    float acc[4][4] = {};
    for (int k0 = 0; k0 < D_IN; k0 += 32) {
        #pragma unroll
        for (int l = 0; l < 2; l++) {
            int fi = l * 256 + tid;        // 0..511 float4s of A tile
            int m = fi >> 3;               // 0..63
            int kq = fi & 7;               // 0..7
            float4 v = make_float4(0.f, 0.f, 0.f, 0.f);
            if (m0 + m < N_NODES)
                v = *(const float4*)&A[(size_t)(m0 + m) * D_IN + k0 + kq * 4];
            As[kq * 4 + 0][m] = v.x;
            As[kq * 4 + 1][m] = v.y;
            As[kq * 4 + 2][m] = v.z;
            As[kq * 4 + 3][m] = v.w;
        }
        #pragma unroll
        for (int l = 0; l < 2; l++) {
            int fi = l * 256 + tid;        // 0..511 float4s of W tile
            int r = fi >> 4;               // 0..31
            int cq = fi & 15;              // 0..15
            float4 v = *(const float4*)&W[(k0 + r) * 64 + cq * 4];
            *(float4*)&Bs[r][cq * 4] = v;
        }
        __syncthreads();
        #pragma unroll
        for (int kk = 0; kk < 32; kk++) {
            float a[4];
            #pragma unroll
            for (int i = 0; i < 4; i++) a[i] = As[kk][ty * 4 + i];
            float4 b = *(float4*)&Bs[kk][tx * 4];
            #pragma unroll
            for (int i = 0; i < 4; i++) {
                acc[i][0] = fmaf(a[i], b.x, acc[i][0]);
                acc[i][1] = fmaf(a[i], b.y, acc[i][1]);
                acc[i][2] = fmaf(a[i], b.z, acc[i][2]);
                acc[i][3] = fmaf(a[i], b.w, acc[i][3]);
            }
        }
        __syncthreads();
    }
    #pragma unroll
    for (int i = 0; i < 4; i++) {
        int row = m0 + ty * 4 + i;
        if (row < N_NODES) {
            float4 v = make_float4(acc[i][0], acc[i][1], acc[i][2], acc[i][3]);
            *(float4*)&g_bufA[(size_t)row * H + tx * 4] = v;
        }
    }
}

// ---------------- aggregation: g_bufA -> selu(segsum + bias) -> g_bufB ----------------
__global__ void k_aggregate(const float* __restrict__ bias) {
    int gwarp = (blockIdx.x * blockDim.x + threadIdx.x) >> 5;
    int lane = threadIdx.x & 31;
    if (gwarp >= N_NODES) return;
    int node = gwarp;
    int s = g_start[node];
    int e = g_start[node + 1];
    float dv = g_dinv[node];
    const float2* xin = (const float2*)g_bufA;
    float2 sv = xin[node * 32 + lane];
    float nself = dv * dv;
    float2 acc;
    acc.x = sv.x * nself;
    acc.y = sv.y * nself;
    int j = s;
    for (; j + 1 < e; j += 2) {
        int s0 = g_src[j], s1 = g_src[j + 1];
        float n0 = g_nrm[j], n1 = g_nrm[j + 1];
        float2 v0 = xin[s0 * 32 + lane];
        float2 v1 = xin[s1 * 32 + lane];
        acc.x = fmaf(v0.x, n0, acc.x);
        acc.y = fmaf(v0.y, n0, acc.y);
        acc.x = fmaf(v1.x, n1, acc.x);
        acc.y = fmaf(v1.y, n1, acc.y);
    }
    if (j < e) {
        int s0 = g_src[j];
        float n0 = g_nrm[j];
        float2 v0 = xin[s0 * 32 + lane];
        acc.x = fmaf(v0.x, n0, acc.x);
        acc.y = fmaf(v0.y, n0, acc.y);
    }
    float b0 = bias[2 * lane], b1 = bias[2 * lane + 1];
    float2 r;
    r.x = selu_f(acc.x + b0);
    r.y = selu_f(acc.y + b1);
    ((float2*)g_bufB)[node * 32 + lane] = r;
}

// ---------------- 64x64 transform: g_bufB @ W -> g_bufA (no bias/act) ----------------
__global__ void k_dense64(const float* __restrict__ W) {
    __shared__ float hs[64][68];
    __shared__ float ws[64][64];
    int m0 = blockIdx.x * 64;
    int tid = threadIdx.x;
    int ty = tid >> 4, tx = tid & 15;
    #pragma unroll
    for (int l = 0; l < 4; l++) {
        int fi = l * 256 + tid;   // 1024 float4s
        int r = fi >> 4;
        int cq = fi & 15;
        float4 v = make_float4(0.f, 0.f, 0.f, 0.f);
        if (m0 + r < N_NODES) v = *(const float4*)&g_bufB[(size_t)(m0 + r) * H + cq * 4];
        *(float4*)&hs[r][cq * 4] = v;
        *(float4*)&ws[r][cq * 4] = *(const float4*)&W[r * 64 + cq * 4];
    }
    __syncthreads();
    float acc[4][4] = {};
    #pragma unroll 4
    for (int k = 0; k < 64; k++) {
        float a[4];
        #pragma unroll
        for (int i = 0; i < 4; i++) a[i] = hs[ty * 4 + i][k];
        float4 b = *(float4*)&ws[k][tx * 4];
        #pragma unroll
        for (int i = 0; i < 4; i++) {
            acc[i][0] = fmaf(a[i], b.x, acc[i][0]);
            acc[i][1] = fmaf(a[i], b.y, acc[i][1]);
            acc[i][2] = fmaf(a[i], b.z, acc[i][2]);
            acc[i][3] = fmaf(a[i], b.w, acc[i][3]);
        }
    }
    #pragma unroll
    for (int i = 0; i < 4; i++) {
        int row = m0 + ty * 4 + i;
        if (row < N_NODES) {
            float4 v = make_float4(acc[i][0], acc[i][1], acc[i][2], acc[i][3]);
            *(float4*)&g_bufA[(size_t)row * H + tx * 4] = v;
        }
    }
}

// ---------------- fused 4-layer MLP: g_bufB -> out ----------------
__global__ void k_mlp4(const float* __restrict__ W0, const float* __restrict__ b0,
                       const float* __restrict__ W1, const float* __restrict__ b1,
                       const float* __restrict__ W2, const float* __restrict__ b2,
                       const float* __restrict__ W3, const float* __restrict__ b3,
                       float* __restrict__ out) {
    __shared__ float hs[64][68];
    __shared__ float ws[64][64];
    int m0 = blockIdx.x * 64;
    int tid = threadIdx.x;
    int ty = tid >> 4, tx = tid & 15;

    #pragma unroll
    for (int l = 0; l < 4; l++) {
        int fi = l * 256 + tid;
        int r = fi >> 4;
        int cq = fi & 15;
        float4 v = make_float4(0.f, 0.f, 0.f, 0.f);
        if (m0 + r < N_NODES) v = *(const float4*)&g_bufB[(size_t)(m0 + r) * H + cq * 4];
        *(float4*)&hs[r][cq * 4] = v;
    }

    const float* Wl[4] = {W0, W1, W2, W3};
    const float* bl[4] = {b0, b1, b2, b3};

    #pragma unroll
    for (int L = 0; L < 4; L++) {
        __syncthreads();
        #pragma unroll
        for (int l = 0; l < 4; l++) {
            int fi = l * 256 + tid;
            *(float4*)&ws[0][fi * 4] = *(const float4*)&Wl[L][fi * 4];
        }
        __syncthreads();
        float acc[4][4] = {};
        #pragma unroll 4
        for (int k = 0; k < 64; k++) {
            float a[4];
            #pragma unroll
            for (int i = 0; i < 4; i++) a[i] = hs[ty * 4 + i][k];
            float4 b = *(float4*)&ws[k][tx * 4];
            #pragma unroll
            for (int i = 0; i < 4; i++) {
                acc[i][0] = fmaf(a[i], b.x, acc[i][0]);
                acc[i][1] = fmaf(a[i], b.y, acc[i][1]);
                acc[i][2] = fmaf(a[i], b.z, acc[i][2]);
                acc[i][3] = fmaf(a[i], b.w, acc[i][3]);
            }
        }
        float4 bb = *(const float4*)&bl[L][tx * 4];
        __syncthreads();
        if (L < 3) {
            #pragma unroll
            for (int i = 0; i < 4; i++) {
                hs[ty * 4 + i][tx * 4 + 0] = selu_f(acc[i][0] + bb.x);
                hs[ty * 4 + i][tx * 4 + 1] = selu_f(acc[i][1] + bb.y);
                hs[ty * 4 + i][tx * 4 + 2] = selu_f(acc[i][2] + bb.z);
                hs[ty * 4 + i][tx * 4 + 3] = selu_f(acc[i][3] + bb.w);
            }
        } else {
            #pragma unroll
            for (int i = 0; i < 4; i++) {
                int row = m0 + ty * 4 + i;
                if (row < N_NODES) {
                    float4 v = make_float4(acc[i][0] + bb.x, acc[i][1] + bb.y,
                                           acc[i][2] + bb.z, acc[i][3] + bb.w);
                    *(float4*)&out[(size_t)row * H + tx * 4] = v;
                }
            }
        }
    }
}

// ---------------- launch ----------------
extern "C" void kernel_launch(void* const* d_in, const int* in_sizes, int n_in,
                              void* d_out, int out_size) {
    const float* x   = (const float*)d_in[0];
    const int*   ei  = (const int*)d_in[1];
    const float* ea  = (const float*)d_in[2];
    const float* gW1 = (const float*)d_in[3];
    const float* gb1 = (const float*)d_in[4];
    const float* gW2 = (const float*)d_in[5];
    const float* gb2 = (const float*)d_in[6];
    const float* W0  = (const float*)d_in[7];
    const float* b0  = (const float*)d_in[8];
    const float* W1  = (const float*)d_in[9];
    const float* b1  = (const float*)d_in[10];
    const float* W2  = (const float*)d_in[11];
    const float* b2  = (const float*)d_in[12];
    const float* W3  = (const float*)d_in[13];
    const float* b3  = (const float*)d_in[14];
    float* out = (float*)d_out;

    const int nodeBlocks = (N_NODES + 255) / 256;     // 196
    const int edgeBlocks = (N_EDGES + 255) / 256;     // 6250
    const int tileBlocks = (N_NODES + 63) / 64;       // 782
    const int warpBlocks = (N_NODES * 32 + 255) / 256;// 6250

    // CSR build (shared by both GCN layers)
    k_init<<<nodeBlocks, 256>>>();
    k_deg_hist<<<edgeBlocks, 256>>>(ei, ea);
    k_dinv<<<nodeBlocks, 256>>>();
    k_scan1<<<SCAN_BLOCKS, 256>>>();
    k_scan2<<<1, 256>>>();
    k_scan3<<<SCAN_BLOCKS, 256>>>();
    k_scatter<<<edgeBlocks, 256>>>(ei, ea);

    // GCN layer 1
    k_gemm512<<<tileBlocks, 256>>>(x, gW1);
    k_aggregate<<<warpBlocks, 256>>>(gb1);
    // GCN layer 2
    k_dense64<<<tileBlocks, 256>>>(gW2);
    k_aggregate<<<warpBlocks, 256>>>(gb2);
    // fused MLP
    k_mlp4<<<tileBlocks, 256>>>(W0, b0, W1, b1, W2, b2, W3, b3, out);
}

// round 8
// speedup vs baseline: 1.4814x; 1.1985x over previous
#include <cuda_runtime.h>
#include <cuda_bf16.h>
#include <cstdint>
#include <stdint.h>

#define N_NODES 50000
#define N_EDGES 1600000
#define D_IN 512
#define H 64

#define SCAN_BLOCKS 196   // ceil(50000/256)

typedef unsigned int u32;

// ---------------- scratch (static device allocations; no cudaMalloc) ----------------
__device__ float g_deg[N_NODES];
__device__ float g_dinv[N_NODES];
__device__ int   g_count[N_NODES];
__device__ int   g_start[N_NODES + 1];
__device__ int   g_cursor[N_NODES];
__device__ int   g_bsum[SCAN_BLOCKS];
__device__ int   g_boff[SCAN_BLOCKS];
__device__ int   g_src[N_EDGES];
__device__ float g_nrm[N_EDGES];
__device__ float g_bufA[N_NODES * H];   // transformed features
__device__ float g_bufB[N_NODES * H];   // aggregated/activated features

__device__ __forceinline__ float selu_f(float x) {
    const float sc = 1.0507009873554805f;
    const float al = 1.6732632423543772f;
    return x > 0.0f ? sc * x : sc * al * (expf(x) - 1.0f);
}

__device__ __forceinline__ u32 cvt_tf32(float x) {
    u32 r;
    asm("cvt.rna.tf32.f32 %0, %1;" : "=r"(r) : "f"(x));
    return r;
}

__device__ __forceinline__ void mma_tf32(float c[4], u32 a0, u32 a1,
                                         u32 a2, u32 a3,
                                         u32 b0, u32 b1) {
    asm volatile(
        "mma.sync.aligned.m16n8k8.row.col.f32.tf32.tf32.f32 "
        "{%0,%1,%2,%3}, {%4,%5,%6,%7}, {%8,%9}, {%0,%1,%2,%3};\n"
        : "+f"(c[0]), "+f"(c[1]), "+f"(c[2]), "+f"(c[3])
        : "r"(a0), "r"(a1), "r"(a2), "r"(a3), "r"(b0), "r"(b1));
}

// ---------------- degree / CSR construction ----------------
__global__ void k_init() {
    int i = blockIdx.x * blockDim.x + threadIdx.x;
    if (i < N_NODES) {
        g_deg[i] = 1.0f;     // self-loop weight
        g_count[i] = 0;
    }
}

__global__ void k_deg_hist(const int* __restrict__ ei, const float* __restrict__ ew) {
    int e = blockIdx.x * blockDim.x + threadIdx.x;
    if (e < N_EDGES) {
        int c = ei[N_EDGES + e];           // target
        atomicAdd(&g_deg[c], ew[e]);
        atomicAdd(&g_count[c], 1);
    }
}

__global__ void k_dinv() {
    int i = blockIdx.x * blockDim.x + threadIdx.x;
    if (i < N_NODES) {
        float d = g_deg[i];
        g_dinv[i] = (d > 0.0f) ? rsqrtf(d) : 0.0f;
    }
}

// ---------------- 3-phase grid scan over g_count -> g_start, g_cursor ----------------
__global__ void k_scan1() {
    __shared__ int s[256];
    int i = blockIdx.x * 256 + threadIdx.x;
    int v = (i < N_NODES) ? g_count[i] : 0;
    s[threadIdx.x] = v;
    __syncthreads();
    #pragma unroll
    for (int off = 128; off > 0; off >>= 1) {
        if (threadIdx.x < off) s[threadIdx.x] += s[threadIdx.x + off];
        __syncthreads();
    }
    if (threadIdx.x == 0) g_bsum[blockIdx.x] = s[0];
}

__global__ void k_scan2() {
    __shared__ int s[256];
    int t = threadIdx.x;
    s[t] = (t < SCAN_BLOCKS) ? g_bsum[t] : 0;
    __syncthreads();
    #pragma unroll
    for (int off = 1; off < 256; off <<= 1) {
        int v = 0;
        if (t >= off) v = s[t - off];
        __syncthreads();
        if (t >= off) s[t] += v;
        __syncthreads();
    }
    if (t < SCAN_BLOCKS) g_boff[t] = (t == 0) ? 0 : s[t - 1];
}

__global__ void k_scan3() {
    __shared__ int s[256];
    int t = threadIdx.x;
    int i = blockIdx.x * 256 + t;
    int v = (i < N_NODES) ? g_count[i] : 0;
    s[t] = v;
    __syncthreads();
    #pragma unroll
    for (int off = 1; off < 256; off <<= 1) {
        int u = 0;
        if (t >= off) u = s[t - off];
        __syncthreads();
        if (t >= off) s[t] += u;
        __syncthreads();
    }
    if (i < N_NODES) {
        int excl = g_boff[blockIdx.x] + s[t] - v;
        g_start[i] = excl;
        g_cursor[i] = excl;
    }
    if (i == N_NODES - 1) g_start[N_NODES] = N_EDGES;
}

__global__ void k_scatter(const int* __restrict__ ei, const float* __restrict__ ew) {
    int e = blockIdx.x * blockDim.x + threadIdx.x;
    if (e < N_EDGES) {
        int r = ei[e];
        int c = ei[N_EDGES + e];
        int pos = atomicAdd(&g_cursor[c], 1);
        g_src[pos] = r;
        g_nrm[pos] = g_dinv[r] * ew[e] * g_dinv[c];
    }
}

// ---------------- tf32 tensor-core GEMM: [N,512] @ [512,64] -> g_bufA (fp32) ---------
// Block: 128 rows x 64 cols, 8 warps; warp w -> rows [16w,16w+16), all 64 cols.
__global__ void k_gemm512_tc(const float* __restrict__ A, const float* __restrict__ W) {
    __shared__ u32 As[128][36];   // [m][k], pad 36 -> conflict-free frag loads
    __shared__ u32 Bs[32][68];    // [k][n]
    int m0 = blockIdx.x * 128;
    int tid = threadIdx.x;
    int warp = tid >> 5, lane = tid & 31;
    int g = lane >> 2, t = lane & 3;
    float c[8][4] = {};

    for (int k0 = 0; k0 < D_IN; k0 += 32) {
        // A tile: 128 x 32 (1024 float4s over 256 threads)
        #pragma unroll
        for (int l = 0; l < 4; l++) {
            int fi = l * 256 + tid;
            int r = fi >> 3, q = fi & 7;
            float4 v = make_float4(0.f, 0.f, 0.f, 0.f);
            if (m0 + r < N_NODES)
                v = *(const float4*)&A[(size_t)(m0 + r) * D_IN + k0 + q * 4];
            As[r][q * 4 + 0] = cvt_tf32(v.x);
            As[r][q * 4 + 1] = cvt_tf32(v.y);
            As[r][q * 4 + 2] = cvt_tf32(v.z);
            As[r][q * 4 + 3] = cvt_tf32(v.w);
        }
        // B tile: 32 x 64 (512 float4s)
        #pragma unroll
        for (int l = 0; l < 2; l++) {
            int fi = l * 256 + tid;
            int r = fi >> 4, q = fi & 15;
            float4 v = *(const float4*)&W[(k0 + r) * 64 + q * 4];
            Bs[r][q * 4 + 0] = cvt_tf32(v.x);
            Bs[r][q * 4 + 1] = cvt_tf32(v.y);
            Bs[r][q * 4 + 2] = cvt_tf32(v.z);
            Bs[r][q * 4 + 3] = cvt_tf32(v.w);
        }
        __syncthreads();
        #pragma unroll
        for (int s = 0; s < 4; s++) {
            u32 a0 = As[warp * 16 + g][s * 8 + t];
            u32 a1 = As[warp * 16 + g + 8][s * 8 + t];
            u32 a2 = As[warp * 16 + g][s * 8 + t + 4];
            u32 a3 = As[warp * 16 + g + 8][s * 8 + t + 4];
            #pragma unroll
            for (int nt = 0; nt < 8; nt++) {
                u32 b0 = Bs[s * 8 + t][nt * 8 + g];
                u32 b1 = Bs[s * 8 + t + 4][nt * 8 + g];
                mma_tf32(c[nt], a0, a1, a2, a3, b0, b1);
            }
        }
        __syncthreads();
    }

    // epilogue: rows rbase+g / rbase+g+8, cols nt*8 + 2t (+1), fp32 float2 stores
    int rbase = m0 + warp * 16;
    int r0 = rbase + g, r1 = rbase + g + 8;
    #pragma unroll
    for (int nt = 0; nt < 8; nt++) {
        int col2 = nt * 4 + t;   // float2 index within the 64-col row
        if (r0 < N_NODES)
            ((float2*)g_bufA)[r0 * 32 + col2] = make_float2(c[nt][0], c[nt][1]);
        if (r1 < N_NODES)
            ((float2*)g_bufA)[r1 * 32 + col2] = make_float2(c[nt][2], c[nt][3]);
    }
}

// ---------------- aggregation: g_bufA -> selu(segsum + bias) -> g_bufB ----------------
__global__ void k_aggregate(const float* __restrict__ bias) {
    int gwarp = (blockIdx.x * blockDim.x + threadIdx.x) >> 5;
    int lane = threadIdx.x & 31;
    if (gwarp >= N_NODES) return;
    int node = gwarp;
    int s = g_start[node];
    int e = g_start[node + 1];
    float dv = g_dinv[node];
    const float2* xin = (const float2*)g_bufA;
    float2 sv = xin[node * 32 + lane];
    float nself = dv * dv;
    float2 acc;
    acc.x = sv.x * nself;
    acc.y = sv.y * nself;
    int j = s;
    for (; j + 1 < e; j += 2) {
        int s0 = g_src[j], s1 = g_src[j + 1];
        float n0 = g_nrm[j], n1 = g_nrm[j + 1];
        float2 v0 = xin[s0 * 32 + lane];
        float2 v1 = xin[s1 * 32 + lane];
        acc.x = fmaf(v0.x, n0, acc.x);
        acc.y = fmaf(v0.y, n0, acc.y);
        acc.x = fmaf(v1.x, n1, acc.x);
        acc.y = fmaf(v1.y, n1, acc.y);
    }
    if (j < e) {
        int s0 = g_src[j];
        float n0 = g_nrm[j];
        float2 v0 = xin[s0 * 32 + lane];
        acc.x = fmaf(v0.x, n0, acc.x);
        acc.y = fmaf(v0.y, n0, acc.y);
    }
    float b0 = bias[2 * lane], b1 = bias[2 * lane + 1];
    float2 r;
    r.x = selu_f(acc.x + b0);
    r.y = selu_f(acc.y + b1);
    ((float2*)g_bufB)[node * 32 + lane] = r;
}

// ---------------- 64x64 transform: g_bufB @ W -> g_bufA (no bias/act) ----------------
__global__ void k_dense64(const float* __restrict__ W) {
    __shared__ float hs[64][68];
    __shared__ float ws[64][64];
    int m0 = blockIdx.x * 64;
    int tid = threadIdx.x;
    int ty = tid >> 4, tx = tid & 15;
    #pragma unroll
    for (int l = 0; l < 4; l++) {
        int fi = l * 256 + tid;   // 1024 float4s
        int r = fi >> 4;
        int cq = fi & 15;
        float4 v = make_float4(0.f, 0.f, 0.f, 0.f);
        if (m0 + r < N_NODES) v = *(const float4*)&g_bufB[(size_t)(m0 + r) * H + cq * 4];
        *(float4*)&hs[r][cq * 4] = v;
        *(float4*)&ws[r][cq * 4] = *(const float4*)&W[r * 64 + cq * 4];
    }
    __syncthreads();
    float acc[4][4] = {};
    #pragma unroll 4
    for (int k = 0; k < 64; k++) {
        float a[4];
        #pragma unroll
        for (int i = 0; i < 4; i++) a[i] = hs[ty * 4 + i][k];
        float4 b = *(float4*)&ws[k][tx * 4];
        #pragma unroll
        for (int i = 0; i < 4; i++) {
            acc[i][0] = fmaf(a[i], b.x, acc[i][0]);
            acc[i][1] = fmaf(a[i], b.y, acc[i][1]);
            acc[i][2] = fmaf(a[i], b.z, acc[i][2]);
            acc[i][3] = fmaf(a[i], b.w, acc[i][3]);
        }
    }
    #pragma unroll
    for (int i = 0; i < 4; i++) {
        int row = m0 + ty * 4 + i;
        if (row < N_NODES) {
            float4 v = make_float4(acc[i][0], acc[i][1], acc[i][2], acc[i][3]);
            *(float4*)&g_bufA[(size_t)row * H + tx * 4] = v;
        }
    }
}

// ---------------- fused 4-layer MLP: g_bufB -> out ----------------
__global__ void k_mlp4(const float* __restrict__ W0, const float* __restrict__ b0,
                       const float* __restrict__ W1, const float* __restrict__ b1,
                       const float* __restrict__ W2, const float* __restrict__ b2,
                       const float* __restrict__ W3, const float* __restrict__ b3,
                       float* __restrict__ out) {
    __shared__ float hs[64][68];
    __shared__ float ws[64][64];
    int m0 = blockIdx.x * 64;
    int tid = threadIdx.x;
    int ty = tid >> 4, tx = tid & 15;

    #pragma unroll
    for (int l = 0; l < 4; l++) {
        int fi = l * 256 + tid;
        int r = fi >> 4;
        int cq = fi & 15;
        float4 v = make_float4(0.f, 0.f, 0.f, 0.f);
        if (m0 + r < N_NODES) v = *(const float4*)&g_bufB[(size_t)(m0 + r) * H + cq * 4];
        *(float4*)&hs[r][cq * 4] = v;
    }

    const float* Wl[4] = {W0, W1, W2, W3};
    const float* bl[4] = {b0, b1, b2, b3};

    #pragma unroll
    for (int L = 0; L < 4; L++) {
        __syncthreads();
        #pragma unroll
        for (int l = 0; l < 4; l++) {
            int fi = l * 256 + tid;
            *(float4*)&ws[0][fi * 4] = *(const float4*)&Wl[L][fi * 4];
        }
        __syncthreads();
        float acc[4][4] = {};
        #pragma unroll 4
        for (int k = 0; k < 64; k++) {
            float a[4];
            #pragma unroll
            for (int i = 0; i < 4; i++) a[i] = hs[ty * 4 + i][k];
            float4 b = *(float4*)&ws[k][tx * 4];
            #pragma unroll
            for (int i = 0; i < 4; i++) {
                acc[i][0] = fmaf(a[i], b.x, acc[i][0]);
                acc[i][1] = fmaf(a[i], b.y, acc[i][1]);
                acc[i][2] = fmaf(a[i], b.z, acc[i][2]);
                acc[i][3] = fmaf(a[i], b.w, acc[i][3]);
            }
        }
        float4 bb = *(const float4*)&bl[L][tx * 4];
        __syncthreads();
        if (L < 3) {
            #pragma unroll
            for (int i = 0; i < 4; i++) {
                hs[ty * 4 + i][tx * 4 + 0] = selu_f(acc[i][0] + bb.x);
                hs[ty * 4 + i][tx * 4 + 1] = selu_f(acc[i][1] + bb.y);
                hs[ty * 4 + i][tx * 4 + 2] = selu_f(acc[i][2] + bb.z);
                hs[ty * 4 + i][tx * 4 + 3] = selu_f(acc[i][3] + bb.w);
            }
        } else {
            #pragma unroll
            for (int i = 0; i < 4; i++) {
                int row = m0 + ty * 4 + i;
                if (row < N_NODES) {
                    float4 v = make_float4(acc[i][0] + bb.x, acc[i][1] + bb.y,
                                           acc[i][2] + bb.z, acc[i][3] + bb.w);
                    *(float4*)&out[(size_t)row * H + tx * 4] = v;
                }
            }
        }
    }
}

// ---------------- launch ----------------
extern "C" void kernel_launch(void* const* d_in, const int* in_sizes, int n_in,
                              void* d_out, int out_size) {
    const float* x   = (const float*)d_in[0];
    const int*   ei  = (const int*)d_in[1];
    const float* ea  = (const float*)d_in[2];
    const float* gW1 = (const float*)d_in[3];
    const float* gb1 = (const float*)d_in[4];
    const float* gW2 = (const float*)d_in[5];
    const float* gb2 = (const float*)d_in[6];
    const float* W0  = (const float*)d_in[7];
    const float* b0  = (const float*)d_in[8];
    const float* W1  = (const float*)d_in[9];
    const float* b1  = (const float*)d_in[10];
    const float* W2  = (const float*)d_in[11];
    const float* b2  = (const float*)d_in[12];
    const float* W3  = (const float*)d_in[13];
    const float* b3  = (const float*)d_in[14];
    float* out = (float*)d_out;

    const int nodeBlocks = (N_NODES + 255) / 256;       // 196
    const int edgeBlocks = (N_EDGES + 255) / 256;       // 6250
    const int tileBlocks = (N_NODES + 63) / 64;         // 782
    const int gemmBlocks = (N_NODES + 127) / 128;       // 391
    const int warpBlocks = (N_NODES * 32 + 255) / 256;  // 6250

    // CSR build (shared by both GCN layers)
    k_init<<<nodeBlocks, 256>>>();
    k_deg_hist<<<edgeBlocks, 256>>>(ei, ea);
    k_dinv<<<nodeBlocks, 256>>>();
    k_scan1<<<SCAN_BLOCKS, 256>>>();
    k_scan2<<<1, 256>>>();
    k_scan3<<<SCAN_BLOCKS, 256>>>();
    k_scatter<<<edgeBlocks, 256>>>(ei, ea);

    // GCN layer 1
    k_gemm512_tc<<<gemmBlocks, 256>>>(x, gW1);
    k_aggregate<<<warpBlocks, 256>>>(gb1);
    // GCN layer 2
    k_dense64<<<tileBlocks, 256>>>(gW2);
    k_aggregate<<<warpBlocks, 256>>>(gb2);
    // fused MLP
    k_mlp4<<<tileBlocks, 256>>>(W0, b0, W1, b1, W2, b2, W3, b3, out);
}

// round 9
// speedup vs baseline: 1.5044x; 1.0155x over previous
#include <cuda_runtime.h>
#include <cuda_fp16.h>
#include <cuda_bf16.h>
#include <cstdint>
#include <stdint.h>

#define N_NODES 50000
#define N_EDGES 1600000
#define D_IN 512
#define H 64

#define SCAN_BLOCKS 196   // ceil(50000/256)

typedef unsigned int u32;

// ---------------- scratch (static device allocations; no cudaMalloc) ----------------
__device__ float   g_deg[N_NODES];
__device__ float   g_dinv[N_NODES];
__device__ int     g_count[N_NODES];
__device__ int     g_start[N_NODES + 1];
__device__ int     g_cursor[N_NODES];
__device__ int     g_bsum[SCAN_BLOCKS];
__device__ int     g_boff[SCAN_BLOCKS];
__device__ int     g_src[N_EDGES];
__device__ float   g_nrm[N_EDGES];
__device__ __half2 g_bufH[N_NODES * 32];   // transformed features (fp16, 64 per node)
__device__ float   g_bufB[N_NODES * H];    // aggregated/activated features (fp32)

__device__ __forceinline__ float selu_f(float x) {
    const float sc = 1.0507009873554805f;
    const float al = 1.6732632423543772f;
    return x > 0.0f ? sc * x : sc * al * (expf(x) - 1.0f);
}

__device__ __forceinline__ u32 cvt_tf32(float x) {
    u32 r;
    asm("cvt.rna.tf32.f32 %0, %1;" : "=r"(r) : "f"(x));
    return r;
}

__device__ __forceinline__ void mma_tf32(float c[4], u32 a0, u32 a1,
                                         u32 a2, u32 a3,
                                         u32 b0, u32 b1) {
    asm volatile(
        "mma.sync.aligned.m16n8k8.row.col.f32.tf32.tf32.f32 "
        "{%0,%1,%2,%3}, {%4,%5,%6,%7}, {%8,%9}, {%0,%1,%2,%3};\n"
        : "+f"(c[0]), "+f"(c[1]), "+f"(c[2]), "+f"(c[3])
        : "r"(a0), "r"(a1), "r"(a2), "r"(a3), "r"(b0), "r"(b1));
}

// ---------------- degree / CSR construction ----------------
__global__ void k_init() {
    int i = blockIdx.x * blockDim.x + threadIdx.x;
    if (i < N_NODES) {
        g_deg[i] = 1.0f;     // self-loop weight
        g_count[i] = 0;
    }
}

__global__ void k_deg_hist(const int* __restrict__ ei, const float* __restrict__ ew) {
    int e = blockIdx.x * blockDim.x + threadIdx.x;
    if (e < N_EDGES) {
        int c = ei[N_EDGES + e];           // target
        atomicAdd(&g_deg[c], ew[e]);
        atomicAdd(&g_count[c], 1);
    }
}

__global__ void k_dinv() {
    int i = blockIdx.x * blockDim.x + threadIdx.x;
    if (i < N_NODES) {
        float d = g_deg[i];
        g_dinv[i] = (d > 0.0f) ? rsqrtf(d) : 0.0f;
    }
}

// ---------------- 3-phase grid scan over g_count -> g_start, g_cursor ----------------
__global__ void k_scan1() {
    __shared__ int s[256];
    int i = blockIdx.x * 256 + threadIdx.x;
    int v = (i < N_NODES) ? g_count[i] : 0;
    s[threadIdx.x] = v;
    __syncthreads();
    #pragma unroll
    for (int off = 128; off > 0; off >>= 1) {
        if (threadIdx.x < off) s[threadIdx.x] += s[threadIdx.x + off];
        __syncthreads();
    }
    if (threadIdx.x == 0) g_bsum[blockIdx.x] = s[0];
}

__global__ void k_scan2() {
    __shared__ int s[256];
    int t = threadIdx.x;
    s[t] = (t < SCAN_BLOCKS) ? g_bsum[t] : 0;
    __syncthreads();
    #pragma unroll
    for (int off = 1; off < 256; off <<= 1) {
        int v = 0;
        if (t >= off) v = s[t - off];
        __syncthreads();
        if (t >= off) s[t] += v;
        __syncthreads();
    }
    if (t < SCAN_BLOCKS) g_boff[t] = (t == 0) ? 0 : s[t - 1];
}

__global__ void k_scan3() {
    __shared__ int s[256];
    int t = threadIdx.x;
    int i = blockIdx.x * 256 + t;
    int v = (i < N_NODES) ? g_count[i] : 0;
    s[t] = v;
    __syncthreads();
    #pragma unroll
    for (int off = 1; off < 256; off <<= 1) {
        int u = 0;
        if (t >= off) u = s[t - off];
        __syncthreads();
        if (t >= off) s[t] += u;
        __syncthreads();
    }
    if (i < N_NODES) {
        int excl = g_boff[blockIdx.x] + s[t] - v;
        g_start[i] = excl;
        g_cursor[i] = excl;
    }
    if (i == N_NODES - 1) g_start[N_NODES] = N_EDGES;
}

__global__ void k_scatter(const int* __restrict__ ei, const float* __restrict__ ew) {
    int e = blockIdx.x * blockDim.x + threadIdx.x;
    if (e < N_EDGES) {
        int r = ei[e];
        int c = ei[N_EDGES + e];
        int pos = atomicAdd(&g_cursor[c], 1);
        g_src[pos] = r;
        g_nrm[pos] = g_dinv[r] * ew[e] * g_dinv[c];
    }
}

// ---------------- tf32 tensor-core GEMM: [N,512] @ [512,64] -> g_bufH (fp16) ---------
// Block: 128 rows x 64 cols, 8 warps; warp w -> rows [16w,16w+16), all 64 cols.
__global__ void k_gemm512_tc(const float* __restrict__ A, const float* __restrict__ W) {
    __shared__ u32 As[128][36];   // [m][k], pad 36 -> conflict-free frag loads
    __shared__ u32 Bs[32][68];    // [k][n]
    int m0 = blockIdx.x * 128;
    int tid = threadIdx.x;
    int warp = tid >> 5, lane = tid & 31;
    int g = lane >> 2, t = lane & 3;
    float c[8][4] = {};

    for (int k0 = 0; k0 < D_IN; k0 += 32) {
        // A tile: 128 x 32 (1024 float4s over 256 threads)
        #pragma unroll
        for (int l = 0; l < 4; l++) {
            int fi = l * 256 + tid;
            int r = fi >> 3, q = fi & 7;
            float4 v = make_float4(0.f, 0.f, 0.f, 0.f);
            if (m0 + r < N_NODES)
                v = *(const float4*)&A[(size_t)(m0 + r) * D_IN + k0 + q * 4];
            As[r][q * 4 + 0] = cvt_tf32(v.x);
            As[r][q * 4 + 1] = cvt_tf32(v.y);
            As[r][q * 4 + 2] = cvt_tf32(v.z);
            As[r][q * 4 + 3] = cvt_tf32(v.w);
        }
        // B tile: 32 x 64 (512 float4s)
        #pragma unroll
        for (int l = 0; l < 2; l++) {
            int fi = l * 256 + tid;
            int r = fi >> 4, q = fi & 15;
            float4 v = *(const float4*)&W[(k0 + r) * 64 + q * 4];
            Bs[r][q * 4 + 0] = cvt_tf32(v.x);
            Bs[r][q * 4 + 1] = cvt_tf32(v.y);
            Bs[r][q * 4 + 2] = cvt_tf32(v.z);
            Bs[r][q * 4 + 3] = cvt_tf32(v.w);
        }
        __syncthreads();
        #pragma unroll
        for (int s = 0; s < 4; s++) {
            u32 a0 = As[warp * 16 + g][s * 8 + t];
            u32 a1 = As[warp * 16 + g + 8][s * 8 + t];
            u32 a2 = As[warp * 16 + g][s * 8 + t + 4];
            u32 a3 = As[warp * 16 + g + 8][s * 8 + t + 4];
            #pragma unroll
            for (int nt = 0; nt < 8; nt++) {
                u32 b0 = Bs[s * 8 + t][nt * 8 + g];
                u32 b1 = Bs[s * 8 + t + 4][nt * 8 + g];
                mma_tf32(c[nt], a0, a1, a2, a3, b0, b1);
            }
        }
        __syncthreads();
    }

    // epilogue: rows rbase+g / rbase+g+8, cols nt*8 + 2t (+1) -> half2
    int rbase = m0 + warp * 16;
    int r0 = rbase + g, r1 = rbase + g + 8;
    #pragma unroll
    for (int nt = 0; nt < 8; nt++) {
        int col2 = nt * 4 + t;   // half2 index within the 32-half2 row
        if (r0 < N_NODES) g_bufH[r0 * 32 + col2] = __floats2half2_rn(c[nt][0], c[nt][1]);
        if (r1 < N_NODES) g_bufH[r1 * 32 + col2] = __floats2half2_rn(c[nt][2], c[nt][3]);
    }
}

// ---------------- aggregation: g_bufH -> selu(segsum + bias) -> g_bufB (fp32) --------
__global__ void k_aggregate(const float* __restrict__ bias) {
    int gwarp = (blockIdx.x * blockDim.x + threadIdx.x) >> 5;
    int lane = threadIdx.x & 31;
    if (gwarp >= N_NODES) return;
    int node = gwarp;
    int s = g_start[node];
    int e = g_start[node + 1];
    float dv = g_dinv[node];
    float2 sv = __half22float2(g_bufH[node * 32 + lane]);
    float nself = dv * dv;
    float2 acc;
    acc.x = sv.x * nself;
    acc.y = sv.y * nself;
    int j = s;
    for (; j + 1 < e; j += 2) {
        int s0 = g_src[j], s1 = g_src[j + 1];
        float n0 = g_nrm[j], n1 = g_nrm[j + 1];
        float2 v0 = __half22float2(g_bufH[s0 * 32 + lane]);
        float2 v1 = __half22float2(g_bufH[s1 * 32 + lane]);
        acc.x = fmaf(v0.x, n0, acc.x);
        acc.y = fmaf(v0.y, n0, acc.y);
        acc.x = fmaf(v1.x, n1, acc.x);
        acc.y = fmaf(v1.y, n1, acc.y);
    }
    if (j < e) {
        int s0 = g_src[j];
        float n0 = g_nrm[j];
        float2 v0 = __half22float2(g_bufH[s0 * 32 + lane]);
        acc.x = fmaf(v0.x, n0, acc.x);
        acc.y = fmaf(v0.y, n0, acc.y);
    }
    float b0 = bias[2 * lane], b1 = bias[2 * lane + 1];
    float2 r;
    r.x = selu_f(acc.x + b0);
    r.y = selu_f(acc.y + b1);
    ((float2*)g_bufB)[node * 32 + lane] = r;
}

// ---------------- 64x64 transform: g_bufB @ W -> g_bufH (fp16 out, no bias/act) ------
__global__ void k_dense64(const float* __restrict__ W) {
    __shared__ float hs[64][68];
    __shared__ float ws[64][64];
    int m0 = blockIdx.x * 64;
    int tid = threadIdx.x;
    int ty = tid >> 4, tx = tid & 15;
    #pragma unroll
    for (int l = 0; l < 4; l++) {
        int fi = l * 256 + tid;   // 1024 float4s
        int r = fi >> 4;
        int cq = fi & 15;
        float4 v = make_float4(0.f, 0.f, 0.f, 0.f);
        if (m0 + r < N_NODES) v = *(const float4*)&g_bufB[(size_t)(m0 + r) * H + cq * 4];
        *(float4*)&hs[r][cq * 4] = v;
        *(float4*)&ws[r][cq * 4] = *(const float4*)&W[r * 64 + cq * 4];
    }
    __syncthreads();
    float acc[4][4] = {};
    #pragma unroll 4
    for (int k = 0; k < 64; k++) {
        float a[4];
        #pragma unroll
        for (int i = 0; i < 4; i++) a[i] = hs[ty * 4 + i][k];
        float4 b = *(float4*)&ws[k][tx * 4];
        #pragma unroll
        for (int i = 0; i < 4; i++) {
            acc[i][0] = fmaf(a[i], b.x, acc[i][0]);
            acc[i][1] = fmaf(a[i], b.y, acc[i][1]);
            acc[i][2] = fmaf(a[i], b.z, acc[i][2]);
            acc[i][3] = fmaf(a[i], b.w, acc[i][3]);
        }
    }
    #pragma unroll
    for (int i = 0; i < 4; i++) {
        int row = m0 + ty * 4 + i;
        if (row < N_NODES) {
            g_bufH[row * 32 + tx * 2 + 0] = __floats2half2_rn(acc[i][0], acc[i][1]);
            g_bufH[row * 32 + tx * 2 + 1] = __floats2half2_rn(acc[i][2], acc[i][3]);
        }
    }
}

// ---------------- fused 4-layer MLP: g_bufB -> out ----------------
__global__ void k_mlp4(const float* __restrict__ W0, const float* __restrict__ b0,
                       const float* __restrict__ W1, const float* __restrict__ b1,
                       const float* __restrict__ W2, const float* __restrict__ b2,
                       const float* __restrict__ W3, const float* __restrict__ b3,
                       float* __restrict__ out) {
    __shared__ float hs[64][68];
    __shared__ float ws[64][64];
    int m0 = blockIdx.x * 64;
    int tid = threadIdx.x;
    int ty = tid >> 4, tx = tid & 15;

    #pragma unroll
    for (int l = 0; l < 4; l++) {
        int fi = l * 256 + tid;
        int r = fi >> 4;
        int cq = fi & 15;
        float4 v = make_float4(0.f, 0.f, 0.f, 0.f);
        if (m0 + r < N_NODES) v = *(const float4*)&g_bufB[(size_t)(m0 + r) * H + cq * 4];
        *(float4*)&hs[r][cq * 4] = v;
    }

    const float* Wl[4] = {W0, W1, W2, W3};
    const float* bl[4] = {b0, b1, b2, b3};

    #pragma unroll
    for (int L = 0; L < 4; L++) {
        __syncthreads();
        #pragma unroll
        for (int l = 0; l < 4; l++) {
            int fi = l * 256 + tid;
            *(float4*)&ws[0][fi * 4] = *(const float4*)&Wl[L][fi * 4];
        }
        __syncthreads();
        float acc[4][4] = {};
        #pragma unroll 4
        for (int k = 0; k < 64; k++) {
            float a[4];
            #pragma unroll
            for (int i = 0; i < 4; i++) a[i] = hs[ty * 4 + i][k];
            float4 b = *(float4*)&ws[k][tx * 4];
            #pragma unroll
            for (int i = 0; i < 4; i++) {
                acc[i][0] = fmaf(a[i], b.x, acc[i][0]);
                acc[i][1] = fmaf(a[i], b.y, acc[i][1]);
                acc[i][2] = fmaf(a[i], b.z, acc[i][2]);
                acc[i][3] = fmaf(a[i], b.w, acc[i][3]);
            }
        }
        float4 bb = *(const float4*)&bl[L][tx * 4];
        __syncthreads();
        if (L < 3) {
            #pragma unroll
            for (int i = 0; i < 4; i++) {
                hs[ty * 4 + i][tx * 4 + 0] = selu_f(acc[i][0] + bb.x);
                hs[ty * 4 + i][tx * 4 + 1] = selu_f(acc[i][1] + bb.y);
                hs[ty * 4 + i][tx * 4 + 2] = selu_f(acc[i][2] + bb.z);
                hs[ty * 4 + i][tx * 4 + 3] = selu_f(acc[i][3] + bb.w);
            }
        } else {
            #pragma unroll
            for (int i = 0; i < 4; i++) {
                int row = m0 + ty * 4 + i;
                if (row < N_NODES) {
                    float4 v = make_float4(acc[i][0] + bb.x, acc[i][1] + bb.y,
                                           acc[i][2] + bb.z, acc[i][3] + bb.w);
                    *(float4*)&out[(size_t)row * H + tx * 4] = v;
                }
            }
        }
    }
}

// ---------------- launch ----------------
extern "C" void kernel_launch(void* const* d_in, const int* in_sizes, int n_in,
                              void* d_out, int out_size) {
    const float* x   = (const float*)d_in[0];
    const int*   ei  = (const int*)d_in[1];
    const float* ea  = (const float*)d_in[2];
    const float* gW1 = (const float*)d_in[3];
    const float* gb1 = (const float*)d_in[4];
    const float* gW2 = (const float*)d_in[5];
    const float* gb2 = (const float*)d_in[6];
    const float* W0  = (const float*)d_in[7];
    const float* b0  = (const float*)d_in[8];
    const float* W1  = (const float*)d_in[9];
    const float* b1  = (const float*)d_in[10];
    const float* W2  = (const float*)d_in[11];
    const float* b2  = (const float*)d_in[12];
    const float* W3  = (const float*)d_in[13];
    const float* b3  = (const float*)d_in[14];
    float* out = (float*)d_out;

    const int nodeBlocks = (N_NODES + 255) / 256;       // 196
    const int edgeBlocks = (N_EDGES + 255) / 256;       // 6250
    const int tileBlocks = (N_NODES + 63) / 64;         // 782
    const int gemmBlocks = (N_NODES + 127) / 128;       // 391
    const int warpBlocks = (N_NODES * 32 + 255) / 256;  // 6250

    // CSR build (shared by both GCN layers)
    k_init<<<nodeBlocks, 256>>>();
    k_deg_hist<<<edgeBlocks, 256>>>(ei, ea);
    k_dinv<<<nodeBlocks, 256>>>();
    k_scan1<<<SCAN_BLOCKS, 256>>>();
    k_scan2<<<1, 256>>>();
    k_scan3<<<SCAN_BLOCKS, 256>>>();
    k_scatter<<<edgeBlocks, 256>>>(ei, ea);

    // GCN layer 1
    k_gemm512_tc<<<gemmBlocks, 256>>>(x, gW1);
    k_aggregate<<<warpBlocks, 256>>>(gb1);
    // GCN layer 2
    k_dense64<<<tileBlocks, 256>>>(gW2);
    k_aggregate<<<warpBlocks, 256>>>(gb2);
    // fused MLP
    k_mlp4<<<tileBlocks, 256>>>(W0, b0, W1, b1, W2, b2, W3, b3, out);
}